// round 2
// baseline (speedup 1.0000x reference)
#include <cuda_runtime.h>
#include <cstdint>

#define NROWS 256
#define DDIM  768
#define KD    128
#define NK    500
#define TK    4
#define RPB   4                 // rows per block
#define NBLK  (NROWS / RPB)     // 64 blocks

// output layout (float32, reference return order)
#define OC_OFF  0
#define IDX_OFF 786432
#define SC_OFF  787456
#define QP_OFF  788480

#define NEG_INF (-3.402823466e38f)

__device__ __forceinline__ bool better(float a, int ia, float b, int ib) {
    return (a > b) || (a == b && ia < ib);
}

// maintain sorted (desc by value, asc by index on ties) top-4 list in registers
__device__ __forceinline__ void insert4(float* v, int* id, float x, int ix) {
    if (!better(x, ix, v[3], id[3])) return;
    v[3] = x; id[3] = ix;
#pragma unroll
    for (int j = 3; j > 0; j--) {
        if (better(v[j], id[j], v[j - 1], id[j - 1])) {
            float tv = v[j]; v[j] = v[j - 1]; v[j - 1] = tv;
            int   ti = id[j]; id[j] = id[j - 1]; id[j - 1] = ti;
        }
    }
}

__global__ __launch_bounds__(256) void fused_kernel(
    const float* __restrict__ regs,
    const float* __restrict__ row_keys,
    const float* __restrict__ col_keys,
    const float* __restrict__ concepts,
    const float* __restrict__ gamma,
    const float* __restrict__ beta,
    const float* __restrict__ Wq,
    const float* __restrict__ bq,
    const float* __restrict__ Wqc,
    const float* __restrict__ bqc,
    float* __restrict__ out)
{
    __shared__ __align__(16) float s_x[RPB][DDIM];     // 12 KB
    __shared__ __align__(16) float s_q[RPB][KD];       // 2 KB
    __shared__ float s_part[2][RPB][KD];               // 4 KB (Q gemm partials)
    __shared__ float s_stat[RPB][2];
    __shared__ float s_tv[RPB][2][TK];
    __shared__ int   s_ti[RPB][2][TK];
    __shared__ int   s_idx[RPB * TK];

    const int t    = threadIdx.x;
    const int warp = t >> 5;
    const int lane = t & 31;
    const int row0 = blockIdx.x * RPB;

    // ---- 1. load 4 input rows (768 float4) ----
    {
        const float4* src = (const float4*)(regs + (size_t)row0 * DDIM);
        float4* dst = (float4*)&s_x[0][0];
        for (int i = t; i < RPB * DDIM / 4; i += 256) dst[i] = src[i];
    }
    __syncthreads();

    // ---- 2. LayerNorm stats (one warp per row) ----
    if (warp < RPB) {
        const int r = warp;
        float s = 0.f;
        for (int j = lane; j < DDIM; j += 32) s += s_x[r][j];
#pragma unroll
        for (int o = 16; o; o >>= 1) s += __shfl_xor_sync(0xffffffffu, s, o);
        const float mu = s * (1.0f / DDIM);
        float vs = 0.f;
        for (int j = lane; j < DDIM; j += 32) { float dv = s_x[r][j] - mu; vs += dv * dv; }
#pragma unroll
        for (int o = 16; o; o >>= 1) vs += __shfl_xor_sync(0xffffffffu, vs, o);
        if (lane == 0) {
            s_stat[r][0] = mu;
            s_stat[r][1] = rsqrtf(vs * (1.0f / DDIM) + 1e-5f);
        }
    }
    __syncthreads();
    // normalize in place
    for (int i = t; i < RPB * DDIM; i += 256) {
        const int r = i / DDIM, d = i - r * DDIM;
        s_x[r][d] = (s_x[r][d] - s_stat[r][0]) * s_stat[r][1] * gamma[d] + beta[d];
    }
    __syncthreads();

    // ---- 3. queries = LN(x) @ Wq + bq  (split D across two thread halves) ----
    {
        const int k    = t & (KD - 1);
        const int half = t >> 7;
        float a0 = 0.f, a1 = 0.f, a2 = 0.f, a3 = 0.f;
        const float4* x0 = (const float4*)&s_x[0][0];
        const float4* x1 = (const float4*)&s_x[1][0];
        const float4* x2 = (const float4*)&s_x[2][0];
        const float4* x3 = (const float4*)&s_x[3][0];
        const int d4b = half * (DDIM / 8);   // 96 float4 per half
        const int d4e = d4b + (DDIM / 8);
        for (int d4 = d4b; d4 < d4e; d4++) {
            const int d = d4 * 4;
            const float w0 = Wq[(d + 0) * KD + k];
            const float w1 = Wq[(d + 1) * KD + k];
            const float w2 = Wq[(d + 2) * KD + k];
            const float w3 = Wq[(d + 3) * KD + k];
            float4 v;
            v = x0[d4]; a0 += v.x * w0 + v.y * w1 + v.z * w2 + v.w * w3;
            v = x1[d4]; a1 += v.x * w0 + v.y * w1 + v.z * w2 + v.w * w3;
            v = x2[d4]; a2 += v.x * w0 + v.y * w1 + v.z * w2 + v.w * w3;
            v = x3[d4]; a3 += v.x * w0 + v.y * w1 + v.z * w2 + v.w * w3;
        }
        s_part[half][0][k] = a0;
        s_part[half][1][k] = a1;
        s_part[half][2][k] = a2;
        s_part[half][3][k] = a3;
    }
    __syncthreads();
    if (t < KD) {
        const float bb = bq[t];
#pragma unroll
        for (int r = 0; r < RPB; r++)
            s_q[r][t] = s_part[0][r][t] + s_part[1][r][t] + bb;
    }
    __syncthreads();

    // ---- 4+5. scores + per-side top-4, coalesced: one warp per (row, side) ----
    // One LDG.128 across the warp covers TWO full 64-dim key rows
    // (lanes 0-15 -> key base+0, lanes 16-31 -> key base+1).
    {
        const int side = warp & 1;
        const int r    = warp >> 1;
        const int sub  = lane >> 4;       // which key of the pair
        const int l16  = lane & 15;
        const float* keys = side ? col_keys : row_keys;

        // per-lane query fragment (4 floats of the relevant 64-dim half)
        const float4 q4 = *(const float4*)&s_q[r][side * 64 + l16 * 4];

        float v[TK]; int id[TK];
#pragma unroll
        for (int j = 0; j < TK; j++) { v[j] = NEG_INF; id[j] = 0x7fffffff; }

#pragma unroll 2
        for (int base = 0; base < NK; base += 2) {
            const float4 k4 = *(const float4*)&keys[(size_t)base * 64 + lane * 4];
            float p = k4.x * q4.x + k4.y * q4.y + k4.z * q4.z + k4.w * q4.w;
            p += __shfl_down_sync(0xffffffffu, p, 8, 16);
            p += __shfl_down_sync(0xffffffffu, p, 4, 16);
            p += __shfl_down_sync(0xffffffffu, p, 2, 16);
            p += __shfl_down_sync(0xffffffffu, p, 1, 16);
            if (l16 == 0) insert4(v, id, p, base + sub);
        }

        // merge lane16's list into lane0 (other lanes hold sentinels)
#pragma unroll
        for (int off = 16; off >= 1; off >>= 1) {
            float ov[TK]; int oi[TK];
#pragma unroll
            for (int j = 0; j < TK; j++) {
                ov[j] = __shfl_down_sync(0xffffffffu, v[j], off);
                oi[j] = __shfl_down_sync(0xffffffffu, id[j], off);
            }
            if (lane < off) {
#pragma unroll
                for (int j = 0; j < TK; j++) insert4(v, id, ov[j], oi[j]);
            }
        }
        if (lane == 0) {
#pragma unroll
            for (int j = 0; j < TK; j++) { s_tv[r][side][j] = v[j]; s_ti[r][side][j] = id[j]; }
        }
    }
    __syncthreads();

    // ---- 6. combine 16 candidates -> final top-4 (value desc, flat idx asc) ----
    if (t < RPB) {
        const int r = t;
        float rv[TK], cv[TK]; int ri[TK], ci[TK];
#pragma unroll
        for (int j = 0; j < TK; j++) {
            rv[j] = s_tv[r][0][j]; ri[j] = s_ti[r][0][j];
            cv[j] = s_tv[r][1][j]; ci[j] = s_ti[r][1][j];
        }
        float bv[TK]; int bi[TK];
#pragma unroll
        for (int j = 0; j < TK; j++) { bv[j] = NEG_INF; bi[j] = 0x7fffffff; }
#pragma unroll
        for (int i = 0; i < TK; i++)
#pragma unroll
            for (int j = 0; j < TK; j++)
                insert4(bv, bi, rv[i] + cv[j], ri[i] * NK + ci[j]);
        const int grow = row0 + r;
#pragma unroll
        for (int n = 0; n < TK; n++) {
            out[SC_OFF  + grow * TK + n] = bv[n];
            out[IDX_OFF + grow * TK + n] = (float)bi[n];
            s_idx[r * TK + n]            = bi[n];
        }
    }
    __syncthreads();

    // ---- 7a. gather concepts[topk_idx] (16 rows x 3KB, overlaps with 7b) ----
    {
        // 16 local rows * 192 float4 = 3072 items; 12 per thread
#pragma unroll
        for (int it = 0; it < (RPB * TK * (DDIM / 4)) / 256; it++) {
            const int i = t + it * 256;
            const int n = i / (DDIM / 4);        // local row 0..15
            const int j = i - n * (DDIM / 4);
            const int cid = s_idx[n];
            const float4 val = *(const float4*)(concepts + (size_t)cid * DDIM + j * 4);
            *(float4*)(out + OC_OFF + ((size_t)(row0 * TK + n)) * DDIM + j * 4) = val;
        }
    }

    // ---- 7b. query_projected = q @ Wqc + bqc ----
    {
        const int o0 = t;  // cols o0, o0+256, o0+512
        float acc[3][RPB];
#pragma unroll
        for (int c = 0; c < 3; c++)
#pragma unroll
            for (int r = 0; r < RPB; r++) acc[c][r] = 0.f;
        for (int j = 0; j < KD; j++) {
            const float q0 = s_q[0][j], q1 = s_q[1][j], q2 = s_q[2][j], q3 = s_q[3][j];
            const float* wr = Wqc + (size_t)j * DDIM;
#pragma unroll
            for (int c = 0; c < 3; c++) {
                const float w = wr[o0 + c * 256];
                acc[c][0] += q0 * w; acc[c][1] += q1 * w;
                acc[c][2] += q2 * w; acc[c][3] += q3 * w;
            }
        }
#pragma unroll
        for (int c = 0; c < 3; c++) {
            const int o = o0 + c * 256;
            const float bb = bqc[o];
#pragma unroll
            for (int r = 0; r < RPB; r++)
                out[QP_OFF + (size_t)(row0 + r) * DDIM + o] = acc[c][r] + bb;
        }
    }
}

extern "C" void kernel_launch(void* const* d_in, const int* in_sizes, int n_in,
                              void* d_out, int out_size) {
    const float* regs     = (const float*)d_in[0];
    const float* row_keys = (const float*)d_in[1];
    const float* col_keys = (const float*)d_in[2];
    const float* concepts = (const float*)d_in[3];
    const float* gamma    = (const float*)d_in[4];
    const float* beta     = (const float*)d_in[5];
    const float* Wq       = (const float*)d_in[6];
    const float* bq       = (const float*)d_in[7];
    const float* Wqc      = (const float*)d_in[8];
    const float* bqc      = (const float*)d_in[9];
    float* out = (float*)d_out;

    fused_kernel<<<NBLK, 256>>>(regs, row_keys, col_keys, concepts, gamma, beta,
                                Wq, bq, Wqc, bqc, out);
}

// round 3
// speedup vs baseline: 2.8262x; 2.8262x over previous
#include <cuda_runtime.h>
#include <cstdint>

#define NROWS 256
#define DDIM  768
#define KD    128
#define NK    500
#define TK    4

// output layout (float32, reference return order)
#define OC_OFF  0
#define IDX_OFF 786432
#define SC_OFF  787456
#define QP_OFF  788480

#define NEG_INF (-3.402823466e38f)

__device__ float g_q[NROWS * KD];          // queries
__device__ float g_sc[2][NROWS][NK];       // row/col scores

__device__ __forceinline__ bool better(float a, int ia, float b, int ib) {
    return (a > b) || (a == b && ia < ib);
}

__device__ __forceinline__ void insert4(float* v, int* id, float x, int ix) {
    if (!better(x, ix, v[3], id[3])) return;
    v[3] = x; id[3] = ix;
#pragma unroll
    for (int j = 3; j > 0; j--) {
        if (better(v[j], id[j], v[j - 1], id[j - 1])) {
            float tv = v[j]; v[j] = v[j - 1]; v[j - 1] = tv;
            int   ti = id[j]; id[j] = id[j - 1]; id[j - 1] = ti;
        }
    }
}

// ---------------------------------------------------------------------------
// K1: LN + Q = LN(x) @ Wq + bq
// grid (4 coltiles of 32, 32 rowtiles of 8), 256 threads
// ---------------------------------------------------------------------------
__global__ __launch_bounds__(256) void k1_ln_q(
    const float* __restrict__ regs,
    const float* __restrict__ gamma,
    const float* __restrict__ beta,
    const float* __restrict__ Wq,
    const float* __restrict__ bq)
{
    __shared__ __align__(16) float sx[8][DDIM];   // 24 KB
    __shared__ __align__(16) float sw[128][32];   // 16 KB
    __shared__ float s_mu[8], s_rs[8];

    const int t  = threadIdx.x;
    const int ct = blockIdx.x;     // 0..3
    const int rt = blockIdx.y;     // 0..31
    const int warp = t >> 5, lane = t & 31;

    // stage 8 input rows (1536 float4)
    {
        const float4* src = (const float4*)(regs + (size_t)rt * 8 * DDIM);
        float4* dst = (float4*)&sx[0][0];
#pragma unroll
        for (int k = 0; k < 6; k++) dst[t + k * 256] = src[t + k * 256];
    }
    __syncthreads();

    // LN stats: warp w handles row w
    {
        float s = 0.f;
        for (int i = lane; i < DDIM; i += 32) s += sx[warp][i];
#pragma unroll
        for (int o = 16; o; o >>= 1) s += __shfl_xor_sync(0xffffffffu, s, o);
        const float mu = s * (1.0f / DDIM);
        float q = 0.f;
        for (int i = lane; i < DDIM; i += 32) { float d = sx[warp][i] - mu; q += d * d; }
#pragma unroll
        for (int o = 16; o; o >>= 1) q += __shfl_xor_sync(0xffffffffu, q, o);
        if (lane == 0) {
            s_mu[warp] = mu;
            s_rs[warp] = rsqrtf(q * (1.0f / DDIM) + 1e-5f);
        }
    }
    __syncthreads();

    // normalize in place: each thread owns d in {t, t+256, t+512} for all 8 rows
    {
        const float g0 = gamma[t], g1 = gamma[t + 256], g2 = gamma[t + 512];
        const float b0 = beta[t],  b1 = beta[t + 256],  b2 = beta[t + 512];
#pragma unroll
        for (int r = 0; r < 8; r++) {
            const float mu = s_mu[r], rs = s_rs[r];
            sx[r][t      ] = (sx[r][t      ] - mu) * rs * g0 + b0;
            sx[r][t + 256] = (sx[r][t + 256] - mu) * rs * g1 + b1;
            sx[r][t + 512] = (sx[r][t + 512] - mu) * rs * g2 + b2;
        }
    }

    // GEMM: thread (rg = t/32 row, c = t%32 col), Wq staged per 128-d chunk
    const int rg = t >> 5, c = t & 31;
    float acc = 0.f;
#pragma unroll 1
    for (int ch = 0; ch < 6; ch++) {
        __syncthreads();
#pragma unroll
        for (int k = 0; k < 4; k++) {
            const int idx = t + k * 256;
            const int wr = idx >> 3, c4 = idx & 7;
            const float4 w = *(const float4*)&Wq[(size_t)(ch * 128 + wr) * KD + ct * 32 + c4 * 4];
            sw[wr][c4 * 4 + 0] = w.x; sw[wr][c4 * 4 + 1] = w.y;
            sw[wr][c4 * 4 + 2] = w.z; sw[wr][c4 * 4 + 3] = w.w;
        }
        __syncthreads();
#pragma unroll 8
        for (int d = 0; d < 128; d++)
            acc += sx[rg][ch * 128 + d] * sw[d][c];
    }
    const int col = ct * 32 + c;
    g_q[(size_t)(rt * 8 + rg) * KD + col] = acc + bq[col];
}

// ---------------------------------------------------------------------------
// K2: row/col scores = q_half @ keys^T
// grid (8 keytiles of 64, 16 rowtiles of 16, 2 sides), 256 threads
// ---------------------------------------------------------------------------
__global__ __launch_bounds__(256) void k2_scores(
    const float* __restrict__ row_keys,
    const float* __restrict__ col_keys)
{
    __shared__ float sk[64][65];   // padded: conflict-free
    __shared__ float sq[16][64];

    const int t    = threadIdx.x;
    const int kt   = blockIdx.x;   // 0..7
    const int rt   = blockIdx.y;   // 0..15
    const int side = blockIdx.z;   // 0..1
    const float* keys = side ? col_keys : row_keys;

    // stage key tile (64 keys x 64 dims), guard OOB keys
#pragma unroll
    for (int k = 0; k < 4; k++) {
        const int idx = t + k * 256;
        const int kl = idx >> 4, d4 = idx & 15;
        const int kg = kt * 64 + kl;
        float4 w = make_float4(0.f, 0.f, 0.f, 0.f);
        if (kg < NK) w = *(const float4*)&keys[(size_t)kg * 64 + d4 * 4];
        sk[kl][d4 * 4 + 0] = w.x; sk[kl][d4 * 4 + 1] = w.y;
        sk[kl][d4 * 4 + 2] = w.z; sk[kl][d4 * 4 + 3] = w.w;
    }
    // stage q tile (16 rows x 64 half-dims)
#pragma unroll
    for (int k = 0; k < 4; k++) {
        const int idx = t + k * 256;
        const int r = idx >> 6, d = idx & 63;
        sq[r][d] = g_q[(size_t)(rt * 16 + r) * KD + side * 64 + d];
    }
    __syncthreads();

    const int g = t >> 6, key = t & 63;
    float a0 = 0.f, a1 = 0.f, a2 = 0.f, a3 = 0.f;
#pragma unroll 8
    for (int d = 0; d < 64; d++) {
        const float kv = sk[key][d];
        a0 += kv * sq[4 * g + 0][d];
        a1 += kv * sq[4 * g + 1][d];
        a2 += kv * sq[4 * g + 2][d];
        a3 += kv * sq[4 * g + 3][d];
    }
    const int kg = kt * 64 + key;
    if (kg < NK) {
        const int r0 = rt * 16 + 4 * g;
        g_sc[side][r0 + 0][kg] = a0;
        g_sc[side][r0 + 1][kg] = a1;
        g_sc[side][r0 + 2][kg] = a2;
        g_sc[side][r0 + 3][kg] = a3;
    }
}

// ---------------------------------------------------------------------------
// K3: per-row top-4 per side, combine 4x4, write idx/scores, gather concepts
// grid 256 (one row), 128 threads
// ---------------------------------------------------------------------------
__global__ __launch_bounds__(128) void k3_topk_gather(
    const float* __restrict__ concepts,
    float* __restrict__ out)
{
    __shared__ float s_tv[2][TK];
    __shared__ int   s_ti[2][TK];
    __shared__ int   s_idx[TK];

    const int row  = blockIdx.x;
    const int t    = threadIdx.x;
    const int warp = t >> 5, lane = t & 31;

    if (warp < 2) {
        const float* sc = &g_sc[warp][row][0];
        float v[TK]; int id[TK];
#pragma unroll
        for (int j = 0; j < TK; j++) { v[j] = NEG_INF; id[j] = 0x7fffffff; }
        for (int i = lane; i < NK; i += 32) insert4(v, id, sc[i], i);
#pragma unroll
        for (int off = 16; off >= 1; off >>= 1) {
            float ov[TK]; int oi[TK];
#pragma unroll
            for (int j = 0; j < TK; j++) {
                ov[j] = __shfl_down_sync(0xffffffffu, v[j], off);
                oi[j] = __shfl_down_sync(0xffffffffu, id[j], off);
            }
            if (lane < off) {
#pragma unroll
                for (int j = 0; j < TK; j++) insert4(v, id, ov[j], oi[j]);
            }
        }
        if (lane == 0) {
#pragma unroll
            for (int j = 0; j < TK; j++) { s_tv[warp][j] = v[j]; s_ti[warp][j] = id[j]; }
        }
    }
    __syncthreads();

    if (t == 0) {
        float bv[TK]; int bi[TK];
#pragma unroll
        for (int j = 0; j < TK; j++) { bv[j] = NEG_INF; bi[j] = 0x7fffffff; }
#pragma unroll
        for (int i = 0; i < TK; i++)
#pragma unroll
            for (int j = 0; j < TK; j++)
                insert4(bv, bi, s_tv[0][i] + s_tv[1][j], s_ti[0][i] * NK + s_ti[1][j]);
#pragma unroll
        for (int n = 0; n < TK; n++) {
            out[SC_OFF  + row * TK + n] = bv[n];
            out[IDX_OFF + row * TK + n] = (float)bi[n];
            s_idx[n] = bi[n];
        }
    }
    __syncthreads();

    // gather 4 concept rows (4 x 192 float4), 6 per thread
#pragma unroll
    for (int k = 0; k < 6; k++) {
        const int i = t + k * 128;
        const int n = i / 192, j = i % 192;
        const int cid = s_idx[n];
        const float4 val = ((const float4*)concepts)[(size_t)cid * 192 + j];
        ((float4*)(out + OC_OFF))[(size_t)(row * TK + n) * 192 + j] = val;
    }
}

// ---------------------------------------------------------------------------
// K4: query_projected = q @ Wqc + bqc
// grid (12 coltiles of 64, 16 rowtiles of 16), 256 threads
// ---------------------------------------------------------------------------
__global__ __launch_bounds__(256) void k4_qp(
    const float* __restrict__ Wqc,
    const float* __restrict__ bqc,
    float* __restrict__ out)
{
    __shared__ float sq[16][KD];   // 8 KB

    const int t  = threadIdx.x;
    const int ct = blockIdx.x;     // 0..11
    const int rt = blockIdx.y;     // 0..15

#pragma unroll
    for (int k = 0; k < 8; k++) {
        const int idx = t + k * 256;
        const int r = idx >> 7, d = idx & 127;
        sq[r][d] = g_q[(size_t)(rt * 16 + r) * KD + d];
    }
    __syncthreads();

    const int g = t >> 6, c = t & 63;
    const int col = ct * 64 + c;
    float a0 = 0.f, a1 = 0.f, a2 = 0.f, a3 = 0.f;
#pragma unroll 4
    for (int d = 0; d < KD; d++) {
        const float w = Wqc[(size_t)d * DDIM + col];
        a0 += sq[4 * g + 0][d] * w;
        a1 += sq[4 * g + 1][d] * w;
        a2 += sq[4 * g + 2][d] * w;
        a3 += sq[4 * g + 3][d] * w;
    }
    const float bb = bqc[col];
    const int r0 = rt * 16 + 4 * g;
    out[QP_OFF + (size_t)(r0 + 0) * DDIM + col] = a0 + bb;
    out[QP_OFF + (size_t)(r0 + 1) * DDIM + col] = a1 + bb;
    out[QP_OFF + (size_t)(r0 + 2) * DDIM + col] = a2 + bb;
    out[QP_OFF + (size_t)(r0 + 3) * DDIM + col] = a3 + bb;
}

extern "C" void kernel_launch(void* const* d_in, const int* in_sizes, int n_in,
                              void* d_out, int out_size) {
    const float* regs     = (const float*)d_in[0];
    const float* row_keys = (const float*)d_in[1];
    const float* col_keys = (const float*)d_in[2];
    const float* concepts = (const float*)d_in[3];
    const float* gamma    = (const float*)d_in[4];
    const float* beta     = (const float*)d_in[5];
    const float* Wq       = (const float*)d_in[6];
    const float* bq       = (const float*)d_in[7];
    const float* Wqc      = (const float*)d_in[8];
    const float* bqc      = (const float*)d_in[9];
    float* out = (float*)d_out;

    k1_ln_q<<<dim3(4, 32), 256>>>(regs, gamma, beta, Wq, bq);
    k2_scores<<<dim3(8, 16, 2), 256>>>(row_keys, col_keys);
    k3_topk_gather<<<256, 128>>>(concepts, out);
    k4_qp<<<dim3(12, 16), 256>>>(Wqc, bqc, out);
}

// round 4
// speedup vs baseline: 3.1541x; 1.1160x over previous
#include <cuda_runtime.h>
#include <cstdint>

#define NROWS 256
#define DDIM  768
#define KD    128
#define NK    500
#define TK    4

// output layout (float32, reference return order)
#define OC_OFF  0
#define IDX_OFF 786432
#define SC_OFF  787456
#define QP_OFF  788480

#define NEG_INF (-3.402823466e38f)

__device__ float g_q[NROWS * KD];          // queries
__device__ float g_sc[2][NROWS][NK];       // row/col scores

__device__ __forceinline__ bool better(float a, int ia, float b, int ib) {
    return (a > b) || (a == b && ia < ib);
}

__device__ __forceinline__ void insert4(float* v, int* id, float x, int ix) {
    if (!better(x, ix, v[3], id[3])) return;
    v[3] = x; id[3] = ix;
#pragma unroll
    for (int j = 3; j > 0; j--) {
        if (better(v[j], id[j], v[j - 1], id[j - 1])) {
            float tv = v[j]; v[j] = v[j - 1]; v[j - 1] = tv;
            int   ti = id[j]; id[j] = id[j - 1]; id[j - 1] = ti;
        }
    }
}

// ---------------------------------------------------------------------------
// K1: LN + Q = LN(x) @ Wq + bq
// grid (4 coltiles of 32, 32 rowtiles of 8), 256 threads
// ---------------------------------------------------------------------------
__global__ __launch_bounds__(256) void k1_ln_q(
    const float* __restrict__ regs,
    const float* __restrict__ gamma,
    const float* __restrict__ beta,
    const float* __restrict__ Wq,
    const float* __restrict__ bq)
{
    __shared__ __align__(16) float sx[8][DDIM];   // 24 KB
    __shared__ __align__(16) float sw[128][32];   // 16 KB
    __shared__ float s_mu[8], s_rs[8];

    const int t  = threadIdx.x;
    const int ct = blockIdx.x;     // 0..3
    const int rt = blockIdx.y;     // 0..31
    const int warp = t >> 5, lane = t & 31;

    // stage 8 input rows (1536 float4)
    {
        const float4* src = (const float4*)(regs + (size_t)rt * 8 * DDIM);
        float4* dst = (float4*)&sx[0][0];
#pragma unroll
        for (int k = 0; k < 6; k++) dst[t + k * 256] = src[t + k * 256];
    }
    __syncthreads();

    // LN stats: warp w handles row w
    {
        float s = 0.f;
        for (int i = lane; i < DDIM; i += 32) s += sx[warp][i];
#pragma unroll
        for (int o = 16; o; o >>= 1) s += __shfl_xor_sync(0xffffffffu, s, o);
        const float mu = s * (1.0f / DDIM);
        float q = 0.f;
        for (int i = lane; i < DDIM; i += 32) { float d = sx[warp][i] - mu; q += d * d; }
#pragma unroll
        for (int o = 16; o; o >>= 1) q += __shfl_xor_sync(0xffffffffu, q, o);
        if (lane == 0) {
            s_mu[warp] = mu;
            s_rs[warp] = rsqrtf(q * (1.0f / DDIM) + 1e-5f);
        }
    }
    __syncthreads();

    // normalize in place
    {
        const float g0 = gamma[t], g1 = gamma[t + 256], g2 = gamma[t + 512];
        const float b0 = beta[t],  b1 = beta[t + 256],  b2 = beta[t + 512];
#pragma unroll
        for (int r = 0; r < 8; r++) {
            const float mu = s_mu[r], rs = s_rs[r];
            sx[r][t      ] = (sx[r][t      ] - mu) * rs * g0 + b0;
            sx[r][t + 256] = (sx[r][t + 256] - mu) * rs * g1 + b1;
            sx[r][t + 512] = (sx[r][t + 512] - mu) * rs * g2 + b2;
        }
    }

    // GEMM: thread (rg = t/32 row, c = t%32 col), Wq staged per 128-d chunk
    const int rg = t >> 5, c = t & 31;
    float acc = 0.f;
    for (int ch = 0; ch < 6; ch++) {
        __syncthreads();
#pragma unroll
        for (int k = 0; k < 4; k++) {
            const int idx = t + k * 256;
            const int wr = idx >> 3, c4 = idx & 7;
            const float4 w = *(const float4*)&Wq[(size_t)(ch * 128 + wr) * KD + ct * 32 + c4 * 4];
            *(float4*)&sw[wr][c4 * 4] = w;
        }
        __syncthreads();
        const float4* xrow = (const float4*)&sx[rg][ch * 128];
#pragma unroll 8
        for (int d4 = 0; d4 < 32; d4++) {
            const float4 xv = xrow[d4];
            acc += xv.x * sw[d4 * 4 + 0][c];
            acc += xv.y * sw[d4 * 4 + 1][c];
            acc += xv.z * sw[d4 * 4 + 2][c];
            acc += xv.w * sw[d4 * 4 + 3][c];
        }
    }
    const int col = ct * 32 + c;
    g_q[(size_t)(rt * 8 + rg) * KD + col] = acc + bq[col];
}

// ---------------------------------------------------------------------------
// KB: merged scores (blocks 0..255) + query_projected (blocks 256..351)
// ---------------------------------------------------------------------------
__global__ __launch_bounds__(256) void kb_scores_qp(
    const float* __restrict__ row_keys,
    const float* __restrict__ col_keys,
    const float* __restrict__ Wqc,
    const float* __restrict__ bqc,
    float* __restrict__ out)
{
    __shared__ float sk[64][65];   // role A: 16.6 KB
    __shared__ float sqa[16][64];  // role A: 4 KB
    __shared__ float sqb[16][KD];  // role B: 8 KB

    const int t = threadIdx.x;
    const int b = blockIdx.x;

    if (b < 256) {
        // ---- role A: scores = q_half @ keys^T ----
        const int kt   = b & 7;          // 0..7
        const int rt   = (b >> 3) & 15;  // 0..15
        const int side = b >> 7;         // 0..1
        const float* keys = side ? col_keys : row_keys;

#pragma unroll
        for (int k = 0; k < 4; k++) {
            const int idx = t + k * 256;
            const int kl = idx >> 4, d4 = idx & 15;
            const int kg = kt * 64 + kl;
            float4 w = make_float4(0.f, 0.f, 0.f, 0.f);
            if (kg < NK) w = *(const float4*)&keys[(size_t)kg * 64 + d4 * 4];
            sk[kl][d4 * 4 + 0] = w.x; sk[kl][d4 * 4 + 1] = w.y;
            sk[kl][d4 * 4 + 2] = w.z; sk[kl][d4 * 4 + 3] = w.w;
        }
#pragma unroll
        for (int k = 0; k < 4; k++) {
            const int idx = t + k * 256;
            const int r = idx >> 6, d = idx & 63;
            sqa[r][d] = g_q[(size_t)(rt * 16 + r) * KD + side * 64 + d];
        }
        __syncthreads();

        const int g = t >> 6, key = t & 63;
        float a0 = 0.f, a1 = 0.f, a2 = 0.f, a3 = 0.f;
#pragma unroll 8
        for (int d = 0; d < 64; d++) {
            const float kv = sk[key][d];
            a0 += kv * sqa[4 * g + 0][d];
            a1 += kv * sqa[4 * g + 1][d];
            a2 += kv * sqa[4 * g + 2][d];
            a3 += kv * sqa[4 * g + 3][d];
        }
        const int kg = kt * 64 + key;
        if (kg < NK) {
            const int r0 = rt * 16 + 4 * g;
            g_sc[side][r0 + 0][kg] = a0;
            g_sc[side][r0 + 1][kg] = a1;
            g_sc[side][r0 + 2][kg] = a2;
            g_sc[side][r0 + 3][kg] = a3;
        }
    } else {
        // ---- role B: query_projected = q @ Wqc + bqc ----
        const int b2 = b - 256;          // 0..95
        const int ct = b2 % 6;           // 128-col tile
        const int rt = b2 / 6;           // 16-row tile

#pragma unroll
        for (int k = 0; k < 8; k++) {
            const int idx = t + k * 256;
            const int r = idx >> 7, d = idx & 127;
            sqb[r][d] = g_q[(size_t)(rt * 16 + r) * KD + d];
        }
        __syncthreads();

        const int ty = t >> 6;           // 0..3 -> 4-row group
        const int tx = t & 63;           // colpair
        const int col = ct * 128 + tx * 2;
        float a00 = 0.f, a01 = 0.f, a10 = 0.f, a11 = 0.f;
        float a20 = 0.f, a21 = 0.f, a30 = 0.f, a31 = 0.f;
        const int r0 = ty * 4;
#pragma unroll 16
        for (int d = 0; d < KD; d++) {
            const float2 w = *(const float2*)&Wqc[(size_t)d * DDIM + col];
            const float q0 = sqb[r0 + 0][d];
            const float q1 = sqb[r0 + 1][d];
            const float q2 = sqb[r0 + 2][d];
            const float q3 = sqb[r0 + 3][d];
            a00 += q0 * w.x; a01 += q0 * w.y;
            a10 += q1 * w.x; a11 += q1 * w.y;
            a20 += q2 * w.x; a21 += q2 * w.y;
            a30 += q3 * w.x; a31 += q3 * w.y;
        }
        const float2 bb = *(const float2*)&bqc[col];
        const int grow = rt * 16 + r0;
        float* o = out + QP_OFF + (size_t)grow * DDIM + col;
        *(float2*)(o + 0 * DDIM) = make_float2(a00 + bb.x, a01 + bb.y);
        *(float2*)(o + 1 * DDIM) = make_float2(a10 + bb.x, a11 + bb.y);
        *(float2*)(o + 2 * DDIM) = make_float2(a20 + bb.x, a21 + bb.y);
        *(float2*)(o + 3 * DDIM) = make_float2(a30 + bb.x, a31 + bb.y);
    }
}

// ---------------------------------------------------------------------------
// KC: per-row top-4 per side, combine 4x4, write idx/scores, gather concepts
// grid 256 (one row), 128 threads
// ---------------------------------------------------------------------------
__global__ __launch_bounds__(128) void kc_topk_gather(
    const float* __restrict__ concepts,
    float* __restrict__ out)
{
    __shared__ float s_tv[2][TK];
    __shared__ int   s_ti[2][TK];
    __shared__ int   s_idx[TK];

    const int row  = blockIdx.x;
    const int t    = threadIdx.x;
    const int warp = t >> 5, lane = t & 31;

    if (warp < 2) {
        const float* sc = &g_sc[warp][row][0];
        float v[TK]; int id[TK];
#pragma unroll
        for (int j = 0; j < TK; j++) { v[j] = NEG_INF; id[j] = 0x7fffffff; }
        for (int i = lane; i < NK; i += 32) insert4(v, id, sc[i], i);
#pragma unroll
        for (int off = 16; off >= 1; off >>= 1) {
            float ov[TK]; int oi[TK];
#pragma unroll
            for (int j = 0; j < TK; j++) {
                ov[j] = __shfl_down_sync(0xffffffffu, v[j], off);
                oi[j] = __shfl_down_sync(0xffffffffu, id[j], off);
            }
            if (lane < off) {
#pragma unroll
                for (int j = 0; j < TK; j++) insert4(v, id, ov[j], oi[j]);
            }
        }
        if (lane == 0) {
#pragma unroll
            for (int j = 0; j < TK; j++) { s_tv[warp][j] = v[j]; s_ti[warp][j] = id[j]; }
        }
    }
    __syncthreads();

    if (t == 0) {
        float bv[TK]; int bi[TK];
#pragma unroll
        for (int j = 0; j < TK; j++) { bv[j] = NEG_INF; bi[j] = 0x7fffffff; }
#pragma unroll
        for (int i = 0; i < TK; i++)
#pragma unroll
            for (int j = 0; j < TK; j++)
                insert4(bv, bi, s_tv[0][i] + s_tv[1][j], s_ti[0][i] * NK + s_ti[1][j]);
#pragma unroll
        for (int n = 0; n < TK; n++) {
            out[SC_OFF  + row * TK + n] = bv[n];
            out[IDX_OFF + row * TK + n] = (float)bi[n];
            s_idx[n] = bi[n];
        }
    }
    __syncthreads();

    // gather 4 concept rows (4 x 192 float4), 6 per thread
#pragma unroll
    for (int k = 0; k < 6; k++) {
        const int i = t + k * 128;
        const int n = i / 192, j = i % 192;
        const int cid = s_idx[n];
        const float4 val = ((const float4*)concepts)[(size_t)cid * 192 + j];
        ((float4*)(out + OC_OFF))[(size_t)(row * TK + n) * 192 + j] = val;
    }
}

extern "C" void kernel_launch(void* const* d_in, const int* in_sizes, int n_in,
                              void* d_out, int out_size) {
    const float* regs     = (const float*)d_in[0];
    const float* row_keys = (const float*)d_in[1];
    const float* col_keys = (const float*)d_in[2];
    const float* concepts = (const float*)d_in[3];
    const float* gamma    = (const float*)d_in[4];
    const float* beta     = (const float*)d_in[5];
    const float* Wq       = (const float*)d_in[6];
    const float* bq       = (const float*)d_in[7];
    const float* Wqc      = (const float*)d_in[8];
    const float* bqc      = (const float*)d_in[9];
    float* out = (float*)d_out;

    k1_ln_q<<<dim3(4, 32), 256>>>(regs, gamma, beta, Wq, bq);
    kb_scores_qp<<<352, 256>>>(row_keys, col_keys, Wqc, bqc, out);
    kc_topk_gather<<<256, 128>>>(concepts, out);
}